// round 2
// baseline (speedup 1.0000x reference)
#include <cuda_runtime.h>
#include <cuda_fp16.h>

#define BB 16
#define MM 2048
#define NN 2048
#define R  16            // rows per CTA in the iteration kernel
#define NITER 100

// Scratch (static __device__ globals -- no runtime allocation)
__device__ __half g_K[(size_t)BB * MM * NN];   // 134 MB fp16 kernel matrix
__device__ float  g_T[3][BB * NN];             // triple-buffered column sums
__device__ float  g_z[BB * MM];                // current z = exp(u)

struct alignas(8) Half4 { __half2 a, b; };

// ---------------------------------------------------------------------------
// K = exp(-C / eps) = exp(-10 C), stored fp16. One float4 per thread.
// ---------------------------------------------------------------------------
__global__ void build_K_kernel(const float* __restrict__ C) {
    size_t i = (size_t)blockIdx.x * blockDim.x + threadIdx.x;   // float4 index
    float4 c = ((const float4*)C)[i];
    __half2 h01 = __floats2half2_rn(__expf(-10.f * c.x), __expf(-10.f * c.y));
    __half2 h23 = __floats2half2_rn(__expf(-10.f * c.z), __expf(-10.f * c.w));
    Half4 o; o.a = h01; o.b = h23;
    ((Half4*)g_K)[i] = o;
}

// ---------------------------------------------------------------------------
// T[0] = b  (so the first iteration sees w = b/T = 1, matching v0 = 0),
// T[1] = T[2] = 0, distance accumulators = 0.
// ---------------------------------------------------------------------------
__global__ void init_kernel(const float* __restrict__ b, float* __restrict__ out) {
    int i = blockIdx.x * blockDim.x + threadIdx.x;   // < BB*NN = 32768
    float bv = b[i];
    g_T[0][i] = bv;
    g_T[1][i] = 0.f;
    g_T[2][i] = 0.f;
    if (i < BB) out[i] = 0.f;
}

// ---------------------------------------------------------------------------
// One Sinkhorn iteration, register-resident tile (no SMEM staging):
//   thread t owns columns [8t, 8t+8) of a 16-row x 2048-col tile.
//   One LDG.128 per row lands the thread's 8 fp16 K values in registers.
//   w_j = b_j / T_in_j              (8 registers)
//   S_i = sum_j K_ij w_j            (phase 1: reg dot + warp/block reduce)
//   z_i = a_i / S_i                 (smem broadcast + g_z store)
//   T_out_j += sum_i K_ij z_i       (phase 2: same registers, 8 atomics)
// Also zeroes its slice of T[zeroIdx] (needed two iterations later).
// Grid: (MM/R, BB) = (128, 16); 256 threads.
// ---------------------------------------------------------------------------
__global__ void __launch_bounds__(256, 2)
sinkhorn_iter(const float* __restrict__ a, const float* __restrict__ b,
              int inIdx, int outIdx, int zeroIdx) {
    __shared__ float red[R * 8];   // 16 rows x 8 warp-partials
    __shared__ float zs[R];

    const int batch = blockIdx.y;
    const int rb    = blockIdx.x;
    const int tid   = threadIdx.x;
    const int warp  = tid >> 5, lane = tid & 31;
    const int row0  = rb * R;

    // Register tile: 16 x uint4 = 16 rows x 8 fp16 columns per thread
    uint4 tile[R];
    const uint4* src = (const uint4*)(g_K + ((size_t)batch * MM + row0) * NN);
    #pragma unroll
    for (int i = 0; i < R; i++)
        tile[i] = src[i * (NN / 8) + tid];

    // w for this thread's 8 contiguous columns
    const float4* b4 = (const float4*)(b + batch * NN);
    const float4* t4 = (const float4*)(g_T[inIdx] + batch * NN);
    float4 bv0 = b4[2 * tid], bv1 = b4[2 * tid + 1];
    float4 tv0 = t4[2 * tid], tv1 = t4[2 * tid + 1];
    float w[8];
    w[0] = __fdividef(bv0.x, tv0.x); w[1] = __fdividef(bv0.y, tv0.y);
    w[2] = __fdividef(bv0.z, tv0.z); w[3] = __fdividef(bv0.w, tv0.w);
    w[4] = __fdividef(bv1.x, tv1.x); w[5] = __fdividef(bv1.y, tv1.y);
    w[6] = __fdividef(bv1.z, tv1.z); w[7] = __fdividef(bv1.w, tv1.w);

    // Zero slice of the buffer used two iterations from now (2048/128 = 16/CTA)
    if (tid < 16) g_T[zeroIdx][batch * NN + rb * 16 + tid] = 0.f;

    // Phase 1: row sums from registers
    #pragma unroll
    for (int i = 0; i < R; i++) {
        const __half2* h = (const __half2*)&tile[i];
        float2 f0 = __half22float2(h[0]);
        float2 f1 = __half22float2(h[1]);
        float2 f2 = __half22float2(h[2]);
        float2 f3 = __half22float2(h[3]);
        float v = f0.x * w[0] + f0.y * w[1] + f1.x * w[2] + f1.y * w[3]
                + f2.x * w[4] + f2.y * w[5] + f3.x * w[6] + f3.y * w[7];
        v += __shfl_xor_sync(0xffffffffu, v, 16);
        v += __shfl_xor_sync(0xffffffffu, v, 8);
        v += __shfl_xor_sync(0xffffffffu, v, 4);
        v += __shfl_xor_sync(0xffffffffu, v, 2);
        v += __shfl_xor_sync(0xffffffffu, v, 1);
        if (lane == 0) red[i * 8 + warp] = v;
    }
    __syncthreads();

    // Second-stage reduce: tid < 128, tid = row*8 + k (8-lane groups warp-aligned)
    if (tid < 128) {
        float v = red[tid];
        v += __shfl_xor_sync(0xffffffffu, v, 4);
        v += __shfl_xor_sync(0xffffffffu, v, 2);
        v += __shfl_xor_sync(0xffffffffu, v, 1);
        if ((tid & 7) == 0) {
            int row = tid >> 3;
            float zi = __fdividef(__ldg(&a[batch * MM + row0 + row]), v);
            zs[row] = zi;
            g_z[batch * MM + row0 + row] = zi;
        }
    }
    __syncthreads();

    // Phase 2: column partials from the same registers
    float acc[8] = {0.f, 0.f, 0.f, 0.f, 0.f, 0.f, 0.f, 0.f};
    #pragma unroll
    for (int i = 0; i < R; i++) {
        float zi = zs[i];
        const __half2* h = (const __half2*)&tile[i];
        float2 f0 = __half22float2(h[0]);
        float2 f1 = __half22float2(h[1]);
        float2 f2 = __half22float2(h[2]);
        float2 f3 = __half22float2(h[3]);
        acc[0] += f0.x * zi; acc[1] += f0.y * zi;
        acc[2] += f1.x * zi; acc[3] += f1.y * zi;
        acc[4] += f2.x * zi; acc[5] += f2.y * zi;
        acc[6] += f3.x * zi; acc[7] += f3.y * zi;
    }
    float* To = g_T[outIdx] + batch * NN + 8 * tid;
    #pragma unroll
    for (int c = 0; c < 8; c++)
        atomicAdd(&To[c], acc[c]);
}

// ---------------------------------------------------------------------------
// P_ij = z_i * exp(-10 C_ij) * w_j  (exact fp32 K for the output),
// distance_b = sum_ij P_ij C_ij.
// Grid: (MM/8, BB); 256 threads; each CTA does 8 rows x 2048 cols.
// ---------------------------------------------------------------------------
__global__ void __launch_bounds__(256)
finalize_kernel(const float* __restrict__ C, const float* __restrict__ b,
                float* __restrict__ out, int tIdx) {
    const int batch = blockIdx.y;
    const int rb    = blockIdx.x;
    const int tid   = threadIdx.x;

    const float4* b4 = (const float4*)(b + batch * NN);
    const float4* t4 = (const float4*)(g_T[tIdx] + batch * NN);
    float4 bv0 = b4[tid], bv1 = b4[tid + 256];
    float4 tv0 = t4[tid], tv1 = t4[tid + 256];
    float4 w0 = make_float4(bv0.x / tv0.x, bv0.y / tv0.y, bv0.z / tv0.z, bv0.w / tv0.w);
    float4 w1 = make_float4(bv1.x / tv1.x, bv1.y / tv1.y, bv1.z / tv1.z, bv1.w / tv1.w);

    const size_t rowbase = (size_t)batch * MM + rb * 8;
    float* P = out + BB;
    float acc = 0.f;

    #pragma unroll
    for (int i = 0; i < 8; i++) {
        float zi = g_z[rowbase + i];
        const float4* Crow = (const float4*)(C + (rowbase + i) * NN);
        float4 c0 = Crow[tid], c1 = Crow[tid + 256];
        float4 p0, p1;
        p0.x = zi * __expf(-10.f * c0.x) * w0.x;
        p0.y = zi * __expf(-10.f * c0.y) * w0.y;
        p0.z = zi * __expf(-10.f * c0.z) * w0.z;
        p0.w = zi * __expf(-10.f * c0.w) * w0.w;
        p1.x = zi * __expf(-10.f * c1.x) * w1.x;
        p1.y = zi * __expf(-10.f * c1.y) * w1.y;
        p1.z = zi * __expf(-10.f * c1.z) * w1.z;
        p1.w = zi * __expf(-10.f * c1.w) * w1.w;
        float4* Prow = (float4*)(P + (rowbase + i) * NN);
        Prow[tid]       = p0;
        Prow[tid + 256] = p1;
        acc += p0.x * c0.x + p0.y * c0.y + p0.z * c0.z + p0.w * c0.w
             + p1.x * c1.x + p1.y * c1.y + p1.z * c1.z + p1.w * c1.w;
    }

    // Block-reduce distance partial, one atomic per CTA per batch
    #pragma unroll
    for (int off = 16; off; off >>= 1)
        acc += __shfl_xor_sync(0xffffffffu, acc, off);
    __shared__ float rbuf[8];
    int warp = tid >> 5, lane = tid & 31;
    if (lane == 0) rbuf[warp] = acc;
    __syncthreads();
    if (tid == 0) {
        float s = 0.f;
        #pragma unroll
        for (int k = 0; k < 8; k++) s += rbuf[k];
        atomicAdd(&out[batch], s);
    }
}

// ---------------------------------------------------------------------------
extern "C" void kernel_launch(void* const* d_in, const int* in_sizes, int n_in,
                              void* d_out, int out_size) {
    const float* C = (const float*)d_in[0];   // (16, 2048, 2048)
    const float* a = (const float*)d_in[1];   // (16, 2048)
    const float* b = (const float*)d_in[2];   // (16, 2048)
    float* out = (float*)d_out;               // [0..16) distance, [16..) P

    // 16*2048*2048 / 4 float4s / 256 threads = 65536 blocks (exact)
    build_K_kernel<<<65536, 256>>>(C);
    init_kernel<<<(BB * NN) / 256, 256>>>(b, out);

    for (int k = 0; k < NITER; k++) {
        sinkhorn_iter<<<dim3(MM / R, BB), 256>>>(
            a, b, k % 3, (k + 1) % 3, (k + 2) % 3);
    }

    finalize_kernel<<<dim3(MM / 8, BB), 256>>>(C, b, out, NITER % 3);
}

// round 3
// speedup vs baseline: 1.5781x; 1.5781x over previous
#include <cuda_runtime.h>
#include <cuda_fp16.h>

#define BB 16
#define MM 2048
#define NN 2048
#define R  16            // rows per CTA in the iteration kernel
#define NITER 100

// Scratch (static __device__ globals -- no runtime allocation)
__device__ __half g_K[(size_t)BB * MM * NN];   // 134 MB fp16 kernel matrix
__device__ float  g_T[3][BB * NN];             // triple-buffered column sums
__device__ float  g_z[BB * MM];                // current z = exp(u)

struct alignas(8) Half4 { __half2 a, b; };

// ---------------------------------------------------------------------------
// K = exp(-C / eps) = exp(-10 C), stored fp16. One float4 per thread.
// ---------------------------------------------------------------------------
__global__ void build_K_kernel(const float* __restrict__ C) {
    size_t i = (size_t)blockIdx.x * blockDim.x + threadIdx.x;   // float4 index
    float4 c = ((const float4*)C)[i];
    __half2 h01 = __floats2half2_rn(__expf(-10.f * c.x), __expf(-10.f * c.y));
    __half2 h23 = __floats2half2_rn(__expf(-10.f * c.z), __expf(-10.f * c.w));
    Half4 o; o.a = h01; o.b = h23;
    ((Half4*)g_K)[i] = o;
}

// ---------------------------------------------------------------------------
// T[0] = b  (so the first iteration sees w = b/T = 1, matching v0 = 0),
// T[1] = T[2] = 0, distance accumulators = 0.
// ---------------------------------------------------------------------------
__global__ void init_kernel(const float* __restrict__ b, float* __restrict__ out) {
    int i = blockIdx.x * blockDim.x + threadIdx.x;   // < BB*NN = 32768
    float bv = b[i];
    g_T[0][i] = bv;
    g_T[1][i] = 0.f;
    g_T[2][i] = 0.f;
    if (i < BB) out[i] = 0.f;
}

// ---------------------------------------------------------------------------
// One Sinkhorn iteration, register-resident tile, occupancy-friendly:
//   thread t owns 4 contiguous columns [4t, 4t+4) of a 16-row tile.
//   One LDG.64 per row (256B/warp, coalesced) -> tile = 16 x uint2 = 32 regs.
//   w_j = b_j / T_in_j              (4 registers)
//   S_i = sum_j K_ij w_j            (phase 1: reg dot + warp/block reduce)
//   z_i = a_i / S_i                 (smem broadcast + g_z store)
//   T_out_j += sum_i K_ij z_i       (phase 2: same registers, 4 atomics)
// Also zeroes its slice of T[zeroIdx] (needed two iterations later).
// Grid: (MM/R, BB) = (128, 16); 512 threads; <=64 regs (2 CTAs/SM).
// ---------------------------------------------------------------------------
__global__ void __launch_bounds__(512, 2)
sinkhorn_iter(const float* __restrict__ a, const float* __restrict__ b,
              int inIdx, int outIdx, int zeroIdx) {
    __shared__ float red[R * 16];  // 16 rows x 16 warp-partials
    __shared__ float zs[R];

    const int batch = blockIdx.y;
    const int rb    = blockIdx.x;
    const int tid   = threadIdx.x;
    const int warp  = tid >> 5, lane = tid & 31;
    const int row0  = rb * R;

    // Register tile: 16 x uint2 = 16 rows x 4 fp16 columns per thread
    uint2 tile[R];
    const uint2* src = (const uint2*)(g_K + ((size_t)batch * MM + row0) * NN);
    #pragma unroll
    for (int i = 0; i < R; i++)
        tile[i] = src[i * (NN / 4) + tid];

    // w for this thread's 4 contiguous columns
    const float4* b4 = (const float4*)(b + batch * NN);
    const float4* t4 = (const float4*)(g_T[inIdx] + batch * NN);
    float4 bv = b4[tid];
    float4 tv = t4[tid];
    float w0 = __fdividef(bv.x, tv.x);
    float w1 = __fdividef(bv.y, tv.y);
    float w2 = __fdividef(bv.z, tv.z);
    float w3 = __fdividef(bv.w, tv.w);

    // Zero slice of the buffer used two iterations from now (2048/128 = 16/CTA)
    if (tid < 16) g_T[zeroIdx][batch * NN + rb * 16 + tid] = 0.f;

    // Phase 1: row sums from registers
    #pragma unroll
    for (int i = 0; i < R; i++) {
        float2 f0 = __half22float2(*(const __half2*)&tile[i].x);
        float2 f1 = __half22float2(*(const __half2*)&tile[i].y);
        float v = f0.x * w0 + f0.y * w1 + f1.x * w2 + f1.y * w3;
        v += __shfl_xor_sync(0xffffffffu, v, 16);
        v += __shfl_xor_sync(0xffffffffu, v, 8);
        v += __shfl_xor_sync(0xffffffffu, v, 4);
        v += __shfl_xor_sync(0xffffffffu, v, 2);
        v += __shfl_xor_sync(0xffffffffu, v, 1);
        if (lane == 0) red[i * 16 + warp] = v;
    }
    __syncthreads();

    // Second stage: 256 partials (16 rows x 16 warps); 16-lane groups stay
    // inside warp halves, so xor-shuffles 8/4/2/1 never cross rows.
    if (tid < 256) {
        float v = red[tid];
        v += __shfl_xor_sync(0xffffffffu, v, 8);
        v += __shfl_xor_sync(0xffffffffu, v, 4);
        v += __shfl_xor_sync(0xffffffffu, v, 2);
        v += __shfl_xor_sync(0xffffffffu, v, 1);
        if ((tid & 15) == 0) {
            int row = tid >> 4;
            float zi = __fdividef(__ldg(&a[batch * MM + row0 + row]), v);
            zs[row] = zi;
            g_z[batch * MM + row0 + row] = zi;
        }
    }
    __syncthreads();

    // Phase 2: column partials from the same registers
    float a0 = 0.f, a1 = 0.f, a2 = 0.f, a3 = 0.f;
    #pragma unroll
    for (int i = 0; i < R; i++) {
        float zi = zs[i];
        float2 f0 = __half22float2(*(const __half2*)&tile[i].x);
        float2 f1 = __half22float2(*(const __half2*)&tile[i].y);
        a0 += f0.x * zi; a1 += f0.y * zi;
        a2 += f1.x * zi; a3 += f1.y * zi;
    }
    float* To = g_T[outIdx] + batch * NN + 4 * tid;
    atomicAdd(&To[0], a0);
    atomicAdd(&To[1], a1);
    atomicAdd(&To[2], a2);
    atomicAdd(&To[3], a3);
}

// ---------------------------------------------------------------------------
// P_ij = z_i * exp(-10 C_ij) * w_j  (exact fp32 K for the output),
// distance_b = sum_ij P_ij C_ij.
// Grid: (MM/8, BB); 256 threads; each CTA does 8 rows x 2048 cols.
// ---------------------------------------------------------------------------
__global__ void __launch_bounds__(256)
finalize_kernel(const float* __restrict__ C, const float* __restrict__ b,
                float* __restrict__ out, int tIdx) {
    const int batch = blockIdx.y;
    const int rb    = blockIdx.x;
    const int tid   = threadIdx.x;

    const float4* b4 = (const float4*)(b + batch * NN);
    const float4* t4 = (const float4*)(g_T[tIdx] + batch * NN);
    float4 bv0 = b4[tid], bv1 = b4[tid + 256];
    float4 tv0 = t4[tid], tv1 = t4[tid + 256];
    float4 w0 = make_float4(bv0.x / tv0.x, bv0.y / tv0.y, bv0.z / tv0.z, bv0.w / tv0.w);
    float4 w1 = make_float4(bv1.x / tv1.x, bv1.y / tv1.y, bv1.z / tv1.z, bv1.w / tv1.w);

    const size_t rowbase = (size_t)batch * MM + rb * 8;
    float* P = out + BB;
    float acc = 0.f;

    #pragma unroll
    for (int i = 0; i < 8; i++) {
        float zi = g_z[rowbase + i];
        const float4* Crow = (const float4*)(C + (rowbase + i) * NN);
        float4 c0 = Crow[tid], c1 = Crow[tid + 256];
        float4 p0, p1;
        p0.x = zi * __expf(-10.f * c0.x) * w0.x;
        p0.y = zi * __expf(-10.f * c0.y) * w0.y;
        p0.z = zi * __expf(-10.f * c0.z) * w0.z;
        p0.w = zi * __expf(-10.f * c0.w) * w0.w;
        p1.x = zi * __expf(-10.f * c1.x) * w1.x;
        p1.y = zi * __expf(-10.f * c1.y) * w1.y;
        p1.z = zi * __expf(-10.f * c1.z) * w1.z;
        p1.w = zi * __expf(-10.f * c1.w) * w1.w;
        float4* Prow = (float4*)(P + (rowbase + i) * NN);
        Prow[tid]       = p0;
        Prow[tid + 256] = p1;
        acc += p0.x * c0.x + p0.y * c0.y + p0.z * c0.z + p0.w * c0.w
             + p1.x * c1.x + p1.y * c1.y + p1.z * c1.z + p1.w * c1.w;
    }

    // Block-reduce distance partial, one atomic per CTA per batch
    #pragma unroll
    for (int off = 16; off; off >>= 1)
        acc += __shfl_xor_sync(0xffffffffu, acc, off);
    __shared__ float rbuf[8];
    int warp = tid >> 5, lane = tid & 31;
    if (lane == 0) rbuf[warp] = acc;
    __syncthreads();
    if (tid == 0) {
        float s = 0.f;
        #pragma unroll
        for (int k = 0; k < 8; k++) s += rbuf[k];
        atomicAdd(&out[batch], s);
    }
}

// ---------------------------------------------------------------------------
extern "C" void kernel_launch(void* const* d_in, const int* in_sizes, int n_in,
                              void* d_out, int out_size) {
    const float* C = (const float*)d_in[0];   // (16, 2048, 2048)
    const float* a = (const float*)d_in[1];   // (16, 2048)
    const float* b = (const float*)d_in[2];   // (16, 2048)
    float* out = (float*)d_out;               // [0..16) distance, [16..) P

    // 16*2048*2048 / 4 float4s / 256 threads = 65536 blocks (exact)
    build_K_kernel<<<65536, 256>>>(C);
    init_kernel<<<(BB * NN) / 256, 256>>>(b, out);

    for (int k = 0; k < NITER; k++) {
        sinkhorn_iter<<<dim3(MM / R, BB), 512>>>(
            a, b, k % 3, (k + 1) % 3, (k + 2) % 3);
    }

    finalize_kernel<<<dim3(MM / 8, BB), 256>>>(C, b, out, NITER % 3);
}

// round 4
// speedup vs baseline: 2.8033x; 1.7764x over previous
#include <cuda_runtime.h>
#include <cuda_fp16.h>

#define BB 16
#define MM 2048
#define NN 2048
#define R  16            // rows per CTA (processed as 2 chunks of 8)
#define NITER 100

// Scratch (static __device__ globals -- no runtime allocation)
__device__ __half g_K[(size_t)BB * MM * NN];   // 134 MB fp16 kernel matrix
__device__ float  g_T[3][BB * NN];             // triple-buffered column sums
__device__ float  g_z[BB * MM];                // current z = exp(u)

struct alignas(8) Half4 { __half2 a, b; };

// ---------------------------------------------------------------------------
// K = exp(-C / eps) = exp(-10 C), stored fp16. One float4 per thread.
// ---------------------------------------------------------------------------
__global__ void build_K_kernel(const float* __restrict__ C) {
    size_t i = (size_t)blockIdx.x * blockDim.x + threadIdx.x;   // float4 index
    float4 c = ((const float4*)C)[i];
    __half2 h01 = __floats2half2_rn(__expf(-10.f * c.x), __expf(-10.f * c.y));
    __half2 h23 = __floats2half2_rn(__expf(-10.f * c.z), __expf(-10.f * c.w));
    Half4 o; o.a = h01; o.b = h23;
    ((Half4*)g_K)[i] = o;
}

// ---------------------------------------------------------------------------
// T[0] = b  (so the first iteration sees w = b/T = 1, matching v0 = 0),
// T[1] = T[2] = 0, distance accumulators = 0.
// ---------------------------------------------------------------------------
__global__ void init_kernel(const float* __restrict__ b, float* __restrict__ out) {
    int i = blockIdx.x * blockDim.x + threadIdx.x;   // < BB*NN = 32768
    float bv = b[i];
    g_T[0][i] = bv;
    g_T[1][i] = 0.f;
    g_T[2][i] = 0.f;
    if (i < BB) out[i] = 0.f;
}

// ---------------------------------------------------------------------------
// One Sinkhorn iteration. Thread t owns 4 contiguous columns [4t, 4t+4).
// 16 rows per CTA processed in 2 chunks of 8 (tile = 8 x uint2 = 16 regs).
// Per chunk:
//   phase 1: per-row 4-col dot -> STS partials -> smem-transpose reduce
//            (2 warps per row, 8 coalesced LDS each) -> z_i = a_i / S_i
//   phase 2: acc_j += K_ij * z_i from the SAME registers (K read once/iter)
// Final: one red.global.add.v4.f32 per thread into T_out (4x fewer L2 atomics).
// Grid: (MM/R, BB) = (128, 16); 512 threads; 3 CTAs/SM.
// ---------------------------------------------------------------------------
__global__ void __launch_bounds__(512, 3)
sinkhorn_iter(const float* __restrict__ a, const float* __restrict__ b,
              int inIdx, int outIdx, int zeroIdx) {
    __shared__ float part[8 * 512];  // [row][tid] partials, 16 KB
    __shared__ float halfs[16];      // two half-sums per row
    __shared__ float zs[8];

    const int batch = blockIdx.y;
    const int rb    = blockIdx.x;
    const int tid   = threadIdx.x;
    const int warp  = tid >> 5, lane = tid & 31;
    const int row0  = rb * R;

    // w for this thread's 4 contiguous columns
    const float4* b4 = (const float4*)(b + batch * NN);
    const float4* t4 = (const float4*)(g_T[inIdx] + batch * NN);
    float4 bv = b4[tid];
    float4 tv = t4[tid];
    const float w0 = __fdividef(bv.x, tv.x);
    const float w1 = __fdividef(bv.y, tv.y);
    const float w2 = __fdividef(bv.z, tv.z);
    const float w3 = __fdividef(bv.w, tv.w);

    // Zero slice of the buffer used two iterations from now (2048/128 = 16/CTA)
    if (tid < 16) g_T[zeroIdx][batch * NN + rb * 16 + tid] = 0.f;

    const uint2* src = (const uint2*)(g_K + ((size_t)batch * MM + row0) * NN);
    float a0 = 0.f, a1 = 0.f, a2 = 0.f, a3 = 0.f;

    #pragma unroll
    for (int c = 0; c < 2; c++) {
        // Register tile: 8 rows x 4 fp16 cols, one coalesced LDG.64 per row
        uint2 tile[8];
        #pragma unroll
        for (int i = 0; i < 8; i++)
            tile[i] = src[(c * 8 + i) * (NN / 4) + tid];

        // Phase 1: per-row 4-col dots -> smem partials
        #pragma unroll
        for (int i = 0; i < 8; i++) {
            float2 f0 = __half22float2(*(const __half2*)&tile[i].x);
            float2 f1 = __half22float2(*(const __half2*)&tile[i].y);
            part[i * 512 + tid] =
                f0.x * w0 + f0.y * w1 + f1.x * w2 + f1.y * w3;
        }
        __syncthreads();

        // Transpose reduce: warp w handles row w>>1, half w&1 (256 partials)
        {
            const float* p = &part[(warp >> 1) * 512 + (warp & 1) * 256 + lane];
            float s = 0.f;
            #pragma unroll
            for (int k = 0; k < 8; k++) s += p[32 * k];
            s += __shfl_xor_sync(0xffffffffu, s, 16);
            s += __shfl_xor_sync(0xffffffffu, s, 8);
            s += __shfl_xor_sync(0xffffffffu, s, 4);
            s += __shfl_xor_sync(0xffffffffu, s, 2);
            s += __shfl_xor_sync(0xffffffffu, s, 1);
            if (lane == 0) halfs[warp] = s;
        }
        __syncthreads();

        if (tid < 8) {
            float S  = halfs[2 * tid] + halfs[2 * tid + 1];
            int   ri = batch * MM + row0 + c * 8 + tid;
            float zi = __fdividef(__ldg(&a[ri]), S);
            zs[tid]  = zi;
            g_z[ri]  = zi;
        }
        __syncthreads();

        // Phase 2: column partials from the same registers
        #pragma unroll
        for (int i = 0; i < 8; i++) {
            float zi = zs[i];
            float2 f0 = __half22float2(*(const __half2*)&tile[i].x);
            float2 f1 = __half22float2(*(const __half2*)&tile[i].y);
            a0 += f0.x * zi; a1 += f0.y * zi;
            a2 += f1.x * zi; a3 += f1.y * zi;
        }
    }

    // One vector reduction per thread (16B-aligned)
    float* To = g_T[outIdx] + batch * NN + 4 * tid;
    asm volatile("red.global.add.v4.f32 [%0], {%1, %2, %3, %4};"
                 :: "l"(To), "f"(a0), "f"(a1), "f"(a2), "f"(a3)
                 : "memory");
}

// ---------------------------------------------------------------------------
// P_ij = z_i * exp(-10 C_ij) * w_j  (exact fp32 K for the output),
// distance_b = sum_ij P_ij C_ij.
// Grid: (MM/8, BB); 256 threads; each CTA does 8 rows x 2048 cols.
// ---------------------------------------------------------------------------
__global__ void __launch_bounds__(256)
finalize_kernel(const float* __restrict__ C, const float* __restrict__ b,
                float* __restrict__ out, int tIdx) {
    const int batch = blockIdx.y;
    const int rb    = blockIdx.x;
    const int tid   = threadIdx.x;

    const float4* b4 = (const float4*)(b + batch * NN);
    const float4* t4 = (const float4*)(g_T[tIdx] + batch * NN);
    float4 bv0 = b4[tid], bv1 = b4[tid + 256];
    float4 tv0 = t4[tid], tv1 = t4[tid + 256];
    float4 w0 = make_float4(bv0.x / tv0.x, bv0.y / tv0.y, bv0.z / tv0.z, bv0.w / tv0.w);
    float4 w1 = make_float4(bv1.x / tv1.x, bv1.y / tv1.y, bv1.z / tv1.z, bv1.w / tv1.w);

    const size_t rowbase = (size_t)batch * MM + rb * 8;
    float* P = out + BB;
    float acc = 0.f;

    #pragma unroll
    for (int i = 0; i < 8; i++) {
        float zi = g_z[rowbase + i];
        const float4* Crow = (const float4*)(C + (rowbase + i) * NN);
        float4 c0 = Crow[tid], c1 = Crow[tid + 256];
        float4 p0, p1;
        p0.x = zi * __expf(-10.f * c0.x) * w0.x;
        p0.y = zi * __expf(-10.f * c0.y) * w0.y;
        p0.z = zi * __expf(-10.f * c0.z) * w0.z;
        p0.w = zi * __expf(-10.f * c0.w) * w0.w;
        p1.x = zi * __expf(-10.f * c1.x) * w1.x;
        p1.y = zi * __expf(-10.f * c1.y) * w1.y;
        p1.z = zi * __expf(-10.f * c1.z) * w1.z;
        p1.w = zi * __expf(-10.f * c1.w) * w1.w;
        float4* Prow = (float4*)(P + (rowbase + i) * NN);
        Prow[tid]       = p0;
        Prow[tid + 256] = p1;
        acc += p0.x * c0.x + p0.y * c0.y + p0.z * c0.z + p0.w * c0.w
             + p1.x * c1.x + p1.y * c1.y + p1.z * c1.z + p1.w * c1.w;
    }

    // Block-reduce distance partial, one atomic per CTA per batch
    #pragma unroll
    for (int off = 16; off; off >>= 1)
        acc += __shfl_xor_sync(0xffffffffu, acc, off);
    __shared__ float rbuf[8];
    int warp = tid >> 5, lane = tid & 31;
    if (lane == 0) rbuf[warp] = acc;
    __syncthreads();
    if (tid == 0) {
        float s = 0.f;
        #pragma unroll
        for (int k = 0; k < 8; k++) s += rbuf[k];
        atomicAdd(&out[batch], s);
    }
}

// ---------------------------------------------------------------------------
extern "C" void kernel_launch(void* const* d_in, const int* in_sizes, int n_in,
                              void* d_out, int out_size) {
    const float* C = (const float*)d_in[0];   // (16, 2048, 2048)
    const float* a = (const float*)d_in[1];   // (16, 2048)
    const float* b = (const float*)d_in[2];   // (16, 2048)
    float* out = (float*)d_out;               // [0..16) distance, [16..) P

    // 16*2048*2048 / 4 float4s / 256 threads = 65536 blocks (exact)
    build_K_kernel<<<65536, 256>>>(C);
    init_kernel<<<(BB * NN) / 256, 256>>>(b, out);

    for (int k = 0; k < NITER; k++) {
        sinkhorn_iter<<<dim3(MM / R, BB), 512>>>(
            a, b, k % 3, (k + 1) % 3, (k + 2) % 3);
    }

    finalize_kernel<<<dim3(MM / 8, BB), 256>>>(C, b, out, NITER % 3);
}